// round 1
// baseline (speedup 1.0000x reference)
#include <cuda_runtime.h>
#include <cuda_bf16.h>
#include <math_constants.h>

// ---------------- problem constants ----------------
#define BATCH_B   4
#define NB        4096
#define NPTS      (BATCH_B * NB)       // 16384
#define MB        1024                 // centroids per cloud
#define MTOT      (BATCH_B * MB)       // 4096
#define DIN       64
#define KNB       64                   // max neighbors
#define H1        128
#define H2        128
#define H3        256

#define X_ELEMS      ((size_t)MTOT * H3)          // 1048576
#define POS_OFF      X_ELEMS
#define POS_ELEMS    ((size_t)MTOT * 3)           // 12288
#define BATCH_OFF    (POS_OFF + POS_ELEMS)        // 1060864
#define BATCH_ELEMS  ((size_t)MTOT)

// ---------------- device scratch (no allocs allowed) ----------------
__device__ int   g_sel[MTOT];                 // selected point index (local to cloud)
__device__ float g_qpos[MTOT * 3];            // centroid xyz
__device__ int   g_nbr[MTOT * KNB];           // neighbor local indices
__device__ int   g_cnt[MTOT];                 // valid neighbor count (<= 64)
__device__ float g_xw1[(size_t)NPTS * H1];    // x @ W1[:64] + b1  (pre-activation)

// exact mul-then-add (match XLA square->sum, no FMA contraction)
__device__ __forceinline__ float d2_exact(float dx, float dy, float dz) {
    return __fadd_rn(__fadd_rn(__fmul_rn(dx, dx), __fmul_rn(dy, dy)), __fmul_rn(dz, dz));
}

// ================= 1) Farthest point sampling =================
// One block per cloud. 1024 threads, 4 points per thread, all state in registers.
__global__ __launch_bounds__(1024, 1)
void fps_kernel(const float* __restrict__ pos) {
    const int b   = blockIdx.x;
    const int tid = threadIdx.x;
    const float* p = pos + (size_t)b * NB * 3;

    float px[4], py[4], pz[4], dd[4];
#pragma unroll
    for (int u = 0; u < 4; u++) {
        int j = u * 1024 + tid;
        px[u] = p[j * 3 + 0];
        py[u] = p[j * 3 + 1];
        pz[u] = p[j * 3 + 2];
        dd[u] = CUDART_INF_F;
    }

    __shared__ float swv[32];
    __shared__ int   swi[32];
    __shared__ float bc[3];
    __shared__ int   sbest;

    if (tid == 0) {
        g_sel[b * MB] = 0;           // sel[0] = 0
        bc[0] = px[0]; bc[1] = py[0]; bc[2] = pz[0];   // p[0] lives in thread 0, u=0
    }
    __syncthreads();

    for (int k = 1; k < MB; k++) {
        const float cx = bc[0], cy = bc[1], cz = bc[2];
        float bv = -1.0f; int bi = 0;
#pragma unroll
        for (int u = 0; u < 4; u++) {
            float d2 = d2_exact(px[u] - cx, py[u] - cy, pz[u] - cz);
            dd[u] = fminf(dd[u], d2);
            if (dd[u] > bv) { bv = dd[u]; bi = u * 1024 + tid; }  // strict > keeps smallest idx
        }
        // warp argmax (tie -> smaller index)
#pragma unroll
        for (int off = 16; off; off >>= 1) {
            float ov = __shfl_down_sync(0xffffffffu, bv, off);
            int   oi = __shfl_down_sync(0xffffffffu, bi, off);
            if (ov > bv || (ov == bv && oi < bi)) { bv = ov; bi = oi; }
        }
        if ((tid & 31) == 0) { swv[tid >> 5] = bv; swi[tid >> 5] = bi; }
        __syncthreads();
        if (tid < 32) {
            bv = swv[tid]; bi = swi[tid];
#pragma unroll
            for (int off = 16; off; off >>= 1) {
                float ov = __shfl_down_sync(0xffffffffu, bv, off);
                int   oi = __shfl_down_sync(0xffffffffu, bi, off);
                if (ov > bv || (ov == bv && oi < bi)) { bv = ov; bi = oi; }
            }
            if (tid == 0) { sbest = bi; g_sel[b * MB + k] = bi; }
        }
        __syncthreads();
        const int widx = sbest;
        if ((widx & 1023) == tid) {
            const int u = widx >> 10;
            if      (u == 0) { bc[0] = px[0]; bc[1] = py[0]; bc[2] = pz[0]; }
            else if (u == 1) { bc[0] = px[1]; bc[1] = py[1]; bc[2] = pz[1]; }
            else if (u == 2) { bc[0] = px[2]; bc[1] = py[2]; bc[2] = pz[2]; }
            else             { bc[0] = px[3]; bc[1] = py[3]; bc[2] = pz[3]; }
        }
        __syncthreads();
    }
}

// ================= 2) Precompute xw1 = x @ W1[:64] + b1 =================
__global__ __launch_bounds__(128)
void xw1_kernel(const float* __restrict__ x, const float* __restrict__ W1,
                const float* __restrict__ b1) {
    const int n = blockIdx.x;
    const int t = threadIdx.x;
    __shared__ float xr[DIN];
    if (t < DIN) xr[t] = x[(size_t)n * DIN + t];
    __syncthreads();
    float acc = __ldg(&b1[t]);
#pragma unroll 8
    for (int i = 0; i < DIN; i++)
        acc = fmaf(xr[i], __ldg(&W1[i * H1 + t]), acc);
    g_xw1[(size_t)n * H1 + t] = acc;
}

// ================= 3) Radius search (first K in index order) =================
__global__ __launch_bounds__(256)
void radius_kernel(const float* __restrict__ pos, float* __restrict__ out, long long out_size) {
    const int warp = (blockIdx.x * blockDim.x + threadIdx.x) >> 5;
    const int lane = threadIdx.x & 31;
    if (warp >= MTOT) return;
    const int b  = warp >> 10;
    const float* p = pos + (size_t)b * NB * 3;

    const int selIdx = g_sel[warp];
    const float qx = p[selIdx * 3 + 0];
    const float qy = p[selIdx * 3 + 1];
    const float qz = p[selIdx * 3 + 2];

    if (lane == 0) {
        g_qpos[warp * 3 + 0] = qx;
        g_qpos[warp * 3 + 1] = qy;
        g_qpos[warp * 3 + 2] = qz;
        if (out_size >= (long long)(POS_OFF + POS_ELEMS)) {
            out[POS_OFF + (size_t)warp * 3 + 0] = qx;
            out[POS_OFF + (size_t)warp * 3 + 1] = qy;
            out[POS_OFF + (size_t)warp * 3 + 2] = qz;
        }
        if (out_size >= (long long)(BATCH_OFF + BATCH_ELEMS)) {
            out[BATCH_OFF + warp] = (float)b;
        }
    }

    const float R2 = 0.04f;   // f32 cast of python 0.2*0.2
    int cnt = 0;
    for (int base = 0; base < NB; base += 32) {
        const int j = base + lane;
        float d2 = d2_exact(p[j * 3 + 0] - qx, p[j * 3 + 1] - qy, p[j * 3 + 2] - qz);
        const bool in = (d2 <= R2);
        const unsigned msk = __ballot_sync(0xffffffffu, in);
        if (in) {
            int r = cnt + __popc(msk & ((1u << lane) - 1u));
            if (r < KNB) g_nbr[warp * KNB + r] = j;
        }
        cnt += __popc(msk);
        if (cnt >= KNB) break;
    }
    if (lane == 0) g_cnt[warp] = cnt < KNB ? cnt : KNB;
}

// ================= 4) Fused PointNetConv: per-centroid MLP + max =================
// Block = 1 centroid, 256 threads. smem: h1T[128][68] + h2T[128][68] + omax[256]
#define PADK 68
__global__ __launch_bounds__(256, 2)
void conv_kernel(const float* __restrict__ pos, const float* __restrict__ W1,
                 const float* __restrict__ W2, const float* __restrict__ b2,
                 const float* __restrict__ W3, const float* __restrict__ b3,
                 float* __restrict__ out) {
    extern __shared__ float sm[];
    float* h1T  = sm;                       // [128][PADK]  feature-major
    float* h2T  = sm + H1 * PADK;           // [128][PADK]
    float* omax = sm + 2 * H1 * PADK;       // [256]

    const int c   = blockIdx.x;
    const int tid = threadIdx.x;
    const int b   = c >> 10;
    const int gp  = b * NB;
    const int count = g_cnt[c];

    const float qx = g_qpos[c * 3 + 0];
    const float qy = g_qpos[c * 3 + 1];
    const float qz = g_qpos[c * 3 + 2];

    if (tid < H3) omax[tid] = 0.0f;  // ReLU outputs >= 0, >=1 valid neighbor always

    // ---- phase 2: h1T[t][k] = relu(xw1[j][t] + rel . W1[64:67][t]) ----
    {
        const int t  = tid & 127;
        const int kh = tid >> 7;                 // 0 or 1: handles 32 k's each
        const float w1x = __ldg(&W1[64 * H1 + t]);
        const float w1y = __ldg(&W1[65 * H1 + t]);
        const float w1z = __ldg(&W1[66 * H1 + t]);
        for (int k = kh * 32; k < kh * 32 + 32; k++) {
            float v = 0.0f;
            if (k < count) {
                const int j = g_nbr[c * KNB + k] + gp;
                const float rx = __ldg(&pos[j * 3 + 0]) - qx;
                const float ry = __ldg(&pos[j * 3 + 1]) - qy;
                const float rz = __ldg(&pos[j * 3 + 2]) - qz;
                v = g_xw1[(size_t)j * H1 + t];
                v = fmaf(rx, w1x, v);
                v = fmaf(ry, w1y, v);
                v = fmaf(rz, w1z, v);
                v = fmaxf(v, 0.0f);
            }
            h1T[t * PADK + k] = v;
        }
    }
    __syncthreads();

    // ---- phase 3: h2 = relu(h1 @ W2 + b2), write transposed h2T[t][k] ----
    {
        const int kt = tid >> 5;          // 8 groups of 8 k
        const int tt = tid & 31;          // 32 groups of 4 t
        const int k0 = kt * 8;
        const int t0 = tt * 4;
        float acc[8][4] = {};
#pragma unroll 4
        for (int i = 0; i < H1; i++) {
            const float4 A0 = *(const float4*)(h1T + i * PADK + k0);
            const float4 A1 = *(const float4*)(h1T + i * PADK + k0 + 4);
            const float4 Bv = __ldg((const float4*)(W2 + i * H2 + t0));
            float a[8] = {A0.x, A0.y, A0.z, A0.w, A1.x, A1.y, A1.z, A1.w};
#pragma unroll
            for (int u = 0; u < 8; u++) {
                acc[u][0] = fmaf(a[u], Bv.x, acc[u][0]);
                acc[u][1] = fmaf(a[u], Bv.y, acc[u][1]);
                acc[u][2] = fmaf(a[u], Bv.z, acc[u][2]);
                acc[u][3] = fmaf(a[u], Bv.w, acc[u][3]);
            }
        }
        const float4 bb = __ldg((const float4*)(b2 + t0));
        const float bv[4] = {bb.x, bb.y, bb.z, bb.w};
#pragma unroll
        for (int u = 0; u < 8; u++)
#pragma unroll
            for (int v = 0; v < 4; v++)
                h2T[(t0 + v) * PADK + (k0 + u)] = fmaxf(acc[u][v] + bv[v], 0.0f);
    }
    __syncthreads();

    // ---- phase 4: h3 = relu(h2 @ W3 + b3), max over valid k ----
    {
        const int kt = tid >> 5;          // 8 groups of 8 k
        const int tt = tid & 31;          // 32 groups of 8 t (256 outputs)
        const int k0 = kt * 8;
        const int t0 = tt * 8;
        float acc[8][8] = {};
#pragma unroll 2
        for (int i = 0; i < H2; i++) {
            const float4 A0 = *(const float4*)(h2T + i * PADK + k0);
            const float4 A1 = *(const float4*)(h2T + i * PADK + k0 + 4);
            const float4 B0 = __ldg((const float4*)(W3 + i * H3 + t0));
            const float4 B1 = __ldg((const float4*)(W3 + i * H3 + t0 + 4));
            float a[8]  = {A0.x, A0.y, A0.z, A0.w, A1.x, A1.y, A1.z, A1.w};
            float bw[8] = {B0.x, B0.y, B0.z, B0.w, B1.x, B1.y, B1.z, B1.w};
#pragma unroll
            for (int u = 0; u < 8; u++)
#pragma unroll
                for (int v = 0; v < 8; v++)
                    acc[u][v] = fmaf(a[u], bw[v], acc[u][v]);
        }
        const float4 c0 = __ldg((const float4*)(b3 + t0));
        const float4 c1 = __ldg((const float4*)(b3 + t0 + 4));
        const float bb[8] = {c0.x, c0.y, c0.z, c0.w, c1.x, c1.y, c1.z, c1.w};
        float mv[8] = {0, 0, 0, 0, 0, 0, 0, 0};
#pragma unroll
        for (int u = 0; u < 8; u++) {
            if (k0 + u < count) {
#pragma unroll
                for (int v = 0; v < 8; v++) {
                    float h = fmaxf(acc[u][v] + bb[v], 0.0f);
                    mv[v] = fmaxf(mv[v], h);
                }
            }
        }
        // non-negative floats: int compare == float compare
#pragma unroll
        for (int v = 0; v < 8; v++)
            atomicMax((int*)&omax[t0 + v], __float_as_int(mv[v]));
    }
    __syncthreads();

    if (tid < H3) out[(size_t)c * H3 + tid] = omax[tid];
}

// ================= launch =================
extern "C" void kernel_launch(void* const* d_in, const int* in_sizes, int n_in,
                              void* d_out, int out_size) {
    const float* x   = (const float*)d_in[0];
    const float* pos = (const float*)d_in[1];
    // d_in[2] = batch (int32), unused: clouds are contiguous equal-sized
    const float* W1  = (const float*)d_in[3];
    const float* b1  = (const float*)d_in[4];
    const float* W2  = (const float*)d_in[5];
    const float* b2  = (const float*)d_in[6];
    const float* W3  = (const float*)d_in[7];
    const float* b3  = (const float*)d_in[8];
    float* out = (float*)d_out;

    const int conv_smem = (2 * H1 * PADK + H3) * (int)sizeof(float);  // 70656 B
    cudaFuncSetAttribute(conv_kernel, cudaFuncAttributeMaxDynamicSharedMemorySize, conv_smem);

    fps_kernel<<<BATCH_B, 1024>>>(pos);
    xw1_kernel<<<NPTS, 128>>>(x, W1, b1);
    radius_kernel<<<MTOT / 8, 256>>>(pos, out, (long long)out_size);
    conv_kernel<<<MTOT, 256, conv_smem>>>(pos, W1, W2, b2, W3, b3, out);
}

// round 2
// speedup vs baseline: 1.3844x; 1.3844x over previous
#include <cuda_runtime.h>
#include <cuda_bf16.h>
#include <math_constants.h>

// ---------------- problem constants ----------------
#define BATCH_B   4
#define NB        4096
#define NPTS      (BATCH_B * NB)       // 16384
#define MB        1024                 // centroids per cloud
#define MTOT      (BATCH_B * MB)       // 4096
#define DIN       64
#define KNB       64                   // max neighbors
#define H1        128
#define H2        128
#define H3        256

#define X_ELEMS      ((size_t)MTOT * H3)          // 1048576
#define POS_OFF      X_ELEMS
#define POS_ELEMS    ((size_t)MTOT * 3)           // 12288
#define BATCH_OFF    (POS_OFF + POS_ELEMS)        // 1060864
#define BATCH_ELEMS  ((size_t)MTOT)

// ---------------- device scratch (no allocs allowed) ----------------
__device__ int   g_sel[MTOT];                 // selected point index (local to cloud)
__device__ float g_qpos[MTOT * 3];            // centroid xyz
__device__ int   g_nbr[MTOT * KNB];           // neighbor local indices
__device__ int   g_cnt[MTOT];                 // valid neighbor count (<= 64)
__device__ float g_xw1[(size_t)NPTS * H1];    // x @ W1[:64] + b1  (pre-activation)

// exact mul-then-add (match XLA square->sum, no FMA contraction)
__device__ __forceinline__ float d2_exact(float dx, float dy, float dz) {
    return __fadd_rn(__fadd_rn(__fmul_rn(dx, dx), __fmul_rn(dy, dy)), __fmul_rn(dz, dz));
}

// ---- packed f32x2 helpers (exact per-lane IEEE rn, sm_103a) ----
__device__ __forceinline__ unsigned long long pack2(float lo, float hi) {
    unsigned long long r;
    asm("mov.b64 %0, {%1, %2};" : "=l"(r) : "f"(lo), "f"(hi));
    return r;
}
__device__ __forceinline__ void unpack2(unsigned long long v, float& lo, float& hi) {
    asm("mov.b64 {%0, %1}, %2;" : "=f"(lo), "=f"(hi) : "l"(v));
}
__device__ __forceinline__ unsigned long long add2(unsigned long long a, unsigned long long b) {
    unsigned long long r;
    asm("add.rn.f32x2 %0, %1, %2;" : "=l"(r) : "l"(a), "l"(b));
    return r;
}
__device__ __forceinline__ unsigned long long mul2(unsigned long long a, unsigned long long b) {
    unsigned long long r;
    asm("mul.rn.f32x2 %0, %1, %2;" : "=l"(r) : "l"(a), "l"(b));
    return r;
}

// ================= 1) Farthest point sampling =================
// One block per cloud, 256 threads, 16 points/thread in registers.
// Single __syncthreads per iteration (double-buffered leader slots).
#define FPT 16   // points per thread
__global__ __launch_bounds__(256, 1)
void fps_kernel(const float* __restrict__ pos) {
    const int b    = blockIdx.x;
    const int tid  = threadIdx.x;
    const int lane = tid & 31;
    const int warp = tid >> 5;
    const float* p = pos + (size_t)b * NB * 3;

    __shared__ float spx[NB], spy[NB], spz[NB];          // 48 KB point cache
    __shared__ unsigned long long sled[2][8];            // leader keys, double-buffered

    float px[FPT], py[FPT], pz[FPT], dd[FPT];
#pragma unroll
    for (int u = 0; u < FPT; u++) {
        const int j = u * 256 + tid;
        const float a0 = p[j * 3 + 0];
        const float a1 = p[j * 3 + 1];
        const float a2 = p[j * 3 + 2];
        px[u] = a0; py[u] = a1; pz[u] = a2;
        spx[j] = a0; spy[j] = a1; spz[j] = a2;
        dd[u] = CUDART_INF_F;
    }
    if (tid == 0) g_sel[b * MB] = 0;
    __syncthreads();

    float cx = spx[0], cy = spy[0], cz = spz[0];

    for (int k = 1; k < MB; k++) {
        const unsigned long long ncx = pack2(-cx, -cx);
        const unsigned long long ncy = pack2(-cy, -cy);
        const unsigned long long ncz = pack2(-cz, -cz);

        // update dd for 16 points (8 packed pairs), exact ((dx*dx+dy*dy)+dz*dz)
#pragma unroll
        for (int q = 0; q < FPT / 2; q++) {
            const int u0 = 2 * q, u1 = 2 * q + 1;
            unsigned long long dx = add2(pack2(px[u0], px[u1]), ncx);
            unsigned long long dy = add2(pack2(py[u0], py[u1]), ncy);
            unsigned long long dz = add2(pack2(pz[u0], pz[u1]), ncz);
            unsigned long long s  = add2(add2(mul2(dx, dx), mul2(dy, dy)), mul2(dz, dz));
            float d0, d1;
            unpack2(s, d0, d1);
            dd[u0] = fminf(dd[u0], d0);
            dd[u1] = fminf(dd[u1], d1);
        }

        // local argmax over 16 values, tree, keep-left on ties (= smallest index)
        float  tv[FPT];
        int    tu[FPT];
#pragma unroll
        for (int u = 0; u < FPT; u++) { tv[u] = dd[u]; tu[u] = u; }
#pragma unroll
        for (int step = 1; step < FPT; step <<= 1) {
#pragma unroll
            for (int u = 0; u < FPT; u += 2 * step) {
                const bool take = tv[u + step] > tv[u];     // strict: left (smaller idx) wins ties
                tv[u] = take ? tv[u + step] : tv[u];
                tu[u] = take ? tu[u + step] : tu[u];
            }
        }
        const int myidx = tu[0] * 256 + tid;
        unsigned long long key =
            ((unsigned long long)__float_as_uint(tv[0]) << 32) |
            (unsigned)(NB - 1 - myidx);                     // tie -> smaller idx wins max

        // warp butterfly max
#pragma unroll
        for (int off = 16; off; off >>= 1) {
            unsigned long long o = __shfl_xor_sync(0xffffffffu, key, off);
            if (o > key) key = o;
        }
        const int par = k & 1;
        if (lane == 0) sled[par][warp] = key;
        __syncthreads();

        // all threads redundantly reduce the 8 leaders
        unsigned long long m = sled[par][0];
#pragma unroll
        for (int w = 1; w < 8; w++) {
            unsigned long long o = sled[par][w];
            if (o > m) m = o;
        }
        const int widx = NB - 1 - (int)(unsigned)(m & 0xffffffffu);
        if (tid == 0) g_sel[b * MB + k] = widx;
        cx = spx[widx]; cy = spy[widx]; cz = spz[widx];     // broadcast LDS
    }
}

// ================= 2) Precompute xw1 = x @ W1[:64] + b1 =================
__global__ __launch_bounds__(128)
void xw1_kernel(const float* __restrict__ x, const float* __restrict__ W1,
                const float* __restrict__ b1) {
    const int n = blockIdx.x;
    const int t = threadIdx.x;
    __shared__ float xr[DIN];
    if (t < DIN) xr[t] = x[(size_t)n * DIN + t];
    __syncthreads();
    float acc = __ldg(&b1[t]);
#pragma unroll 8
    for (int i = 0; i < DIN; i++)
        acc = fmaf(xr[i], __ldg(&W1[i * H1 + t]), acc);
    g_xw1[(size_t)n * H1 + t] = acc;
}

// ================= 3) Radius search (first K in index order) =================
__global__ __launch_bounds__(256)
void radius_kernel(const float* __restrict__ pos, float* __restrict__ out, long long out_size) {
    const int warp = (blockIdx.x * blockDim.x + threadIdx.x) >> 5;
    const int lane = threadIdx.x & 31;
    if (warp >= MTOT) return;
    const int b  = warp >> 10;
    const float* p = pos + (size_t)b * NB * 3;

    const int selIdx = g_sel[warp];
    const float qx = p[selIdx * 3 + 0];
    const float qy = p[selIdx * 3 + 1];
    const float qz = p[selIdx * 3 + 2];

    if (lane == 0) {
        g_qpos[warp * 3 + 0] = qx;
        g_qpos[warp * 3 + 1] = qy;
        g_qpos[warp * 3 + 2] = qz;
        if (out_size >= (long long)(POS_OFF + POS_ELEMS)) {
            out[POS_OFF + (size_t)warp * 3 + 0] = qx;
            out[POS_OFF + (size_t)warp * 3 + 1] = qy;
            out[POS_OFF + (size_t)warp * 3 + 2] = qz;
        }
        if (out_size >= (long long)(BATCH_OFF + BATCH_ELEMS)) {
            out[BATCH_OFF + warp] = (float)b;
        }
    }

    const float R2 = 0.04f;   // f32 cast of python 0.2*0.2
    int cnt = 0;
    for (int base = 0; base < NB; base += 32) {
        const int j = base + lane;
        float d2 = d2_exact(p[j * 3 + 0] - qx, p[j * 3 + 1] - qy, p[j * 3 + 2] - qz);
        const bool in = (d2 <= R2);
        const unsigned msk = __ballot_sync(0xffffffffu, in);
        if (in) {
            int r = cnt + __popc(msk & ((1u << lane) - 1u));
            if (r < KNB) g_nbr[warp * KNB + r] = j;
        }
        cnt += __popc(msk);
        if (cnt >= KNB) break;
    }
    if (lane == 0) g_cnt[warp] = cnt < KNB ? cnt : KNB;
}

// ================= 4) Fused PointNetConv: per-centroid MLP + max =================
// Block = 1 centroid, 256 threads. smem: h1T[128][68] + h2T[128][68] + omax[256]
#define PADK 68
__global__ __launch_bounds__(256, 2)
void conv_kernel(const float* __restrict__ pos, const float* __restrict__ W1,
                 const float* __restrict__ W2, const float* __restrict__ b2,
                 const float* __restrict__ W3, const float* __restrict__ b3,
                 float* __restrict__ out) {
    extern __shared__ float sm[];
    float* h1T  = sm;                       // [128][PADK]  feature-major
    float* h2T  = sm + H1 * PADK;           // [128][PADK]
    float* omax = sm + 2 * H1 * PADK;       // [256]

    const int c   = blockIdx.x;
    const int tid = threadIdx.x;
    const int b   = c >> 10;
    const int gp  = b * NB;
    const int count = g_cnt[c];

    const float qx = g_qpos[c * 3 + 0];
    const float qy = g_qpos[c * 3 + 1];
    const float qz = g_qpos[c * 3 + 2];

    if (tid < H3) omax[tid] = 0.0f;  // ReLU outputs >= 0, >=1 valid neighbor always

    // ---- phase 2: h1T[t][k] = relu(xw1[j][t] + rel . W1[64:67][t]) ----
    {
        const int t  = tid & 127;
        const int kh = tid >> 7;                 // 0 or 1: handles 32 k's each
        const float w1x = __ldg(&W1[64 * H1 + t]);
        const float w1y = __ldg(&W1[65 * H1 + t]);
        const float w1z = __ldg(&W1[66 * H1 + t]);
        for (int k = kh * 32; k < kh * 32 + 32; k++) {
            float v = 0.0f;
            if (k < count) {
                const int j = g_nbr[c * KNB + k] + gp;
                const float rx = __ldg(&pos[j * 3 + 0]) - qx;
                const float ry = __ldg(&pos[j * 3 + 1]) - qy;
                const float rz = __ldg(&pos[j * 3 + 2]) - qz;
                v = g_xw1[(size_t)j * H1 + t];
                v = fmaf(rx, w1x, v);
                v = fmaf(ry, w1y, v);
                v = fmaf(rz, w1z, v);
                v = fmaxf(v, 0.0f);
            }
            h1T[t * PADK + k] = v;
        }
    }
    __syncthreads();

    // ---- phase 3: h2 = relu(h1 @ W2 + b2), write transposed h2T[t][k] ----
    {
        const int kt = tid >> 5;          // 8 groups of 8 k
        const int tt = tid & 31;          // 32 groups of 4 t
        const int k0 = kt * 8;
        const int t0 = tt * 4;
        float acc[8][4] = {};
#pragma unroll 4
        for (int i = 0; i < H1; i++) {
            const float4 A0 = *(const float4*)(h1T + i * PADK + k0);
            const float4 A1 = *(const float4*)(h1T + i * PADK + k0 + 4);
            const float4 Bv = __ldg((const float4*)(W2 + i * H2 + t0));
            float a[8] = {A0.x, A0.y, A0.z, A0.w, A1.x, A1.y, A1.z, A1.w};
#pragma unroll
            for (int u = 0; u < 8; u++) {
                acc[u][0] = fmaf(a[u], Bv.x, acc[u][0]);
                acc[u][1] = fmaf(a[u], Bv.y, acc[u][1]);
                acc[u][2] = fmaf(a[u], Bv.z, acc[u][2]);
                acc[u][3] = fmaf(a[u], Bv.w, acc[u][3]);
            }
        }
        const float4 bb = __ldg((const float4*)(b2 + t0));
        const float bv[4] = {bb.x, bb.y, bb.z, bb.w};
#pragma unroll
        for (int u = 0; u < 8; u++)
#pragma unroll
            for (int v = 0; v < 4; v++)
                h2T[(t0 + v) * PADK + (k0 + u)] = fmaxf(acc[u][v] + bv[v], 0.0f);
    }
    __syncthreads();

    // ---- phase 4: h3 = relu(h2 @ W3 + b3), max over valid k ----
    {
        const int kt = tid >> 5;          // 8 groups of 8 k
        const int tt = tid & 31;          // 32 groups of 8 t (256 outputs)
        const int k0 = kt * 8;
        const int t0 = tt * 8;
        float acc[8][8] = {};
#pragma unroll 2
        for (int i = 0; i < H2; i++) {
            const float4 A0 = *(const float4*)(h2T + i * PADK + k0);
            const float4 A1 = *(const float4*)(h2T + i * PADK + k0 + 4);
            const float4 B0 = __ldg((const float4*)(W3 + i * H3 + t0));
            const float4 B1 = __ldg((const float4*)(W3 + i * H3 + t0 + 4));
            float a[8]  = {A0.x, A0.y, A0.z, A0.w, A1.x, A1.y, A1.z, A1.w};
            float bw[8] = {B0.x, B0.y, B0.z, B0.w, B1.x, B1.y, B1.z, B1.w};
#pragma unroll
            for (int u = 0; u < 8; u++)
#pragma unroll
                for (int v = 0; v < 8; v++)
                    acc[u][v] = fmaf(a[u], bw[v], acc[u][v]);
        }
        const float4 c0 = __ldg((const float4*)(b3 + t0));
        const float4 c1 = __ldg((const float4*)(b3 + t0 + 4));
        const float bb[8] = {c0.x, c0.y, c0.z, c0.w, c1.x, c1.y, c1.z, c1.w};
        float mv[8] = {0, 0, 0, 0, 0, 0, 0, 0};
#pragma unroll
        for (int u = 0; u < 8; u++) {
            if (k0 + u < count) {
#pragma unroll
                for (int v = 0; v < 8; v++) {
                    float h = fmaxf(acc[u][v] + bb[v], 0.0f);
                    mv[v] = fmaxf(mv[v], h);
                }
            }
        }
        // non-negative floats: int compare == float compare
#pragma unroll
        for (int v = 0; v < 8; v++)
            atomicMax((int*)&omax[t0 + v], __float_as_int(mv[v]));
    }
    __syncthreads();

    if (tid < H3) out[(size_t)c * H3 + tid] = omax[tid];
}

// ================= launch =================
extern "C" void kernel_launch(void* const* d_in, const int* in_sizes, int n_in,
                              void* d_out, int out_size) {
    const float* x   = (const float*)d_in[0];
    const float* pos = (const float*)d_in[1];
    // d_in[2] = batch (int32), unused: clouds are contiguous equal-sized
    const float* W1  = (const float*)d_in[3];
    const float* b1  = (const float*)d_in[4];
    const float* W2  = (const float*)d_in[5];
    const float* b2  = (const float*)d_in[6];
    const float* W3  = (const float*)d_in[7];
    const float* b3  = (const float*)d_in[8];
    float* out = (float*)d_out;

    const int conv_smem = (2 * H1 * PADK + H3) * (int)sizeof(float);  // 70656 B
    cudaFuncSetAttribute(conv_kernel, cudaFuncAttributeMaxDynamicSharedMemorySize, conv_smem);

    fps_kernel<<<BATCH_B, 256>>>(pos);
    xw1_kernel<<<NPTS, 128>>>(x, W1, b1);
    radius_kernel<<<MTOT / 8, 256>>>(pos, out, (long long)out_size);
    conv_kernel<<<MTOT, 256, conv_smem>>>(pos, W1, W2, b2, W3, b3, out);
}

// round 4
// speedup vs baseline: 2.1974x; 1.5872x over previous
#include <cuda_runtime.h>
#include <cuda_bf16.h>
#include <math_constants.h>
#include <cstdint>

// ---------------- problem constants ----------------
#define BATCH_B   4
#define NB        4096
#define NPTS      (BATCH_B * NB)       // 16384
#define MBQ       1024                 // centroids per cloud
#define MTOT      (BATCH_B * MBQ)      // 4096
#define DIN       64
#define KNB       64
#define H1        128
#define H2        128
#define H3        256
#define LDA       136                  // padded row stride (bf16 elems), 272B

#define POS_OFF      ((size_t)MTOT * H3)
#define POS_ELEMS    ((size_t)MTOT * 3)
#define BATCH_OFF    (POS_OFF + POS_ELEMS)
#define BATCH_ELEMS  ((size_t)MTOT)

// ---------------- device scratch ----------------
__device__ int   g_sel[MTOT];
__device__ float g_qpos[MTOT * 3];
__device__ int   g_nbr[MTOT * KNB];
__device__ int   g_cnt[MTOT];
__device__ float g_xw1[(size_t)NPTS * H1];
// pre-split, pre-transposed weights: WT[n][k] padded to LDA
__device__ __align__(16) __nv_bfloat16 g_w2t_hi[H2 * LDA];
__device__ __align__(16) __nv_bfloat16 g_w2t_lo[H2 * LDA];
__device__ __align__(16) __nv_bfloat16 g_w3t_hi[H3 * LDA];
__device__ __align__(16) __nv_bfloat16 g_w3t_lo[H3 * LDA];

// exact mul-then-add (match XLA square->sum, no FMA contraction)
__device__ __forceinline__ float d2_exact(float dx, float dy, float dz) {
    return __fadd_rn(__fadd_rn(__fmul_rn(dx, dx), __fmul_rn(dy, dy)), __fmul_rn(dz, dz));
}

// ---- packed f32x2 helpers (FPS) ----
__device__ __forceinline__ unsigned long long pack2(float lo, float hi) {
    unsigned long long r;
    asm("mov.b64 %0, {%1, %2};" : "=l"(r) : "f"(lo), "f"(hi));
    return r;
}
__device__ __forceinline__ void unpack2(unsigned long long v, float& lo, float& hi) {
    asm("mov.b64 {%0, %1}, %2;" : "=f"(lo), "=f"(hi) : "l"(v));
}
__device__ __forceinline__ unsigned long long add2(unsigned long long a, unsigned long long b) {
    unsigned long long r;
    asm("add.rn.f32x2 %0, %1, %2;" : "=l"(r) : "l"(a), "l"(b));
    return r;
}
__device__ __forceinline__ unsigned long long mul2(unsigned long long a, unsigned long long b) {
    unsigned long long r;
    asm("mul.rn.f32x2 %0, %1, %2;" : "=l"(r) : "l"(a), "l"(b));
    return r;
}

// ---- mma/ldmatrix helpers (portable PTX, works on compute_103) ----
__device__ __forceinline__ uint32_t smem_u32(const void* p) {
    uint32_t a;
    asm("{ .reg .u64 t; cvta.to.shared.u64 t, %1; cvt.u32.u64 %0, t; }" : "=r"(a) : "l"(p));
    return a;
}
__device__ __forceinline__ void ldmat4(uint32_t* r, uint32_t a) {
    asm volatile("ldmatrix.sync.aligned.m8n8.x4.shared.b16 {%0,%1,%2,%3}, [%4];"
                 : "=r"(r[0]), "=r"(r[1]), "=r"(r[2]), "=r"(r[3]) : "r"(a));
}
__device__ __forceinline__ void mma16816(float* d, const uint32_t* a, const uint32_t* b) {
    asm volatile(
        "mma.sync.aligned.m16n8k16.row.col.f32.bf16.bf16.f32 "
        "{%0,%1,%2,%3}, {%4,%5,%6,%7}, {%8,%9}, {%0,%1,%2,%3};"
        : "+f"(d[0]), "+f"(d[1]), "+f"(d[2]), "+f"(d[3])
        : "r"(a[0]), "r"(a[1]), "r"(a[2]), "r"(a[3]), "r"(b[0]), "r"(b[1]));
}
__device__ __forceinline__ void split_bf16(float v, __nv_bfloat16& hi, __nv_bfloat16& lo) {
    hi = __float2bfloat16_rn(v);
    lo = __float2bfloat16_rn(v - __bfloat162float(hi));
}
__device__ __forceinline__ uint32_t packbf(__nv_bfloat16 a, __nv_bfloat16 b) {
    __nv_bfloat162 t;
    t.x = a; t.y = b;
    return *(uint32_t*)&t;
}

// ================= 1) fused: FPS (blocks 0-3) + xw1/W-prep (blocks 4..147) ===
#define FPT 16
#define NPREP 144
__global__ __launch_bounds__(256, 1)
void fused_fps_prep(const float* __restrict__ pos, const float* __restrict__ x,
                    const float* __restrict__ W1, const float* __restrict__ b1,
                    const float* __restrict__ W2, const float* __restrict__ W3) {
    __shared__ float spx[NB], spy[NB], spz[NB];
    __shared__ unsigned long long sled[2][8];

    if (blockIdx.x < 4) {
        // ---------------- FPS ----------------
        const int b    = blockIdx.x;
        const int tid  = threadIdx.x;
        const int lane = tid & 31;
        const int warp = tid >> 5;
        const float* p = pos + (size_t)b * NB * 3;

        float px[FPT], py[FPT], pz[FPT], dd[FPT];
#pragma unroll
        for (int u = 0; u < FPT; u++) {
            const int j = u * 256 + tid;
            const float a0 = p[j * 3 + 0];
            const float a1 = p[j * 3 + 1];
            const float a2 = p[j * 3 + 2];
            px[u] = a0; py[u] = a1; pz[u] = a2;
            spx[j] = a0; spy[j] = a1; spz[j] = a2;
            dd[u] = CUDART_INF_F;
        }
        if (tid == 0) g_sel[b * MBQ] = 0;
        __syncthreads();

        float cx = spx[0], cy = spy[0], cz = spz[0];

        for (int k = 1; k < MBQ; k++) {
            const unsigned long long ncx = pack2(-cx, -cx);
            const unsigned long long ncy = pack2(-cy, -cy);
            const unsigned long long ncz = pack2(-cz, -cz);
#pragma unroll
            for (int q = 0; q < FPT / 2; q++) {
                const int u0 = 2 * q, u1 = 2 * q + 1;
                unsigned long long dx = add2(pack2(px[u0], px[u1]), ncx);
                unsigned long long dy = add2(pack2(py[u0], py[u1]), ncy);
                unsigned long long dz = add2(pack2(pz[u0], pz[u1]), ncz);
                unsigned long long s  = add2(add2(mul2(dx, dx), mul2(dy, dy)), mul2(dz, dz));
                float d0, d1;
                unpack2(s, d0, d1);
                dd[u0] = fminf(dd[u0], d0);
                dd[u1] = fminf(dd[u1], d1);
            }
            // local argmax (tree, keep-left on tie = smallest index)
            float tv[FPT]; int tu[FPT];
#pragma unroll
            for (int u = 0; u < FPT; u++) { tv[u] = dd[u]; tu[u] = u; }
#pragma unroll
            for (int step = 1; step < FPT; step <<= 1) {
#pragma unroll
                for (int u = 0; u < FPT; u += 2 * step) {
                    const bool take = tv[u + step] > tv[u];
                    tv[u] = take ? tv[u + step] : tv[u];
                    tu[u] = take ? tu[u + step] : tu[u];
                }
            }
            const int myidx = tu[0] * 256 + tid;
            const unsigned vb = __float_as_uint(tv[0]);       // d2 >= 0: uint order == float order
            const unsigned mx = __reduce_max_sync(0xffffffffu, vb);
            const unsigned cand = (vb == mx) ? (unsigned)myidx : 0xffffffffu;
            const unsigned imin = __reduce_min_sync(0xffffffffu, cand);

            const int par = k & 1;
            if (lane == 0)
                sled[par][warp] = ((unsigned long long)mx << 32) | (unsigned)(NB - 1 - imin);
            __syncthreads();

            unsigned long long m = sled[par][0];
#pragma unroll
            for (int w = 1; w < 8; w++) {
                unsigned long long o = sled[par][w];
                if (o > m) m = o;
            }
            const int widx = NB - 1 - (int)(unsigned)(m & 0xffffffffu);
            if (tid == 0) g_sel[b * MBQ + k] = widx;
            cx = spx[widx]; cy = spy[widx]; cz = spz[widx];
        }
    } else {
        // ---------------- prep: xw1 + weight split/transpose ----------------
        const int pb  = blockIdx.x - 4;          // 0..NPREP-1
        const int tid = threadIdx.x;
        const int t   = tid & 127;
        const int rh  = tid >> 7;

        for (int rp = pb; rp < NPTS / 2; rp += NPREP) {
            const int row = rp * 2 + rh;
            float acc = __ldg(&b1[t]);
            const float* xr = x + (size_t)row * DIN;
#pragma unroll 8
            for (int i = 0; i < DIN; i++)
                acc = fmaf(__ldg(&xr[i]), __ldg(&W1[i * H1 + t]), acc);
            g_xw1[(size_t)row * H1 + t] = acc;
        }

        for (int idx = pb * 256 + tid; idx < H2 * H1 + H3 * H2; idx += NPREP * 256) {
            if (idx < H2 * H1) {
                const int n = idx & 127, k = idx >> 7;
                __nv_bfloat16 hi, lo;
                split_bf16(__ldg(&W2[k * H2 + n]), hi, lo);
                g_w2t_hi[n * LDA + k] = hi;
                g_w2t_lo[n * LDA + k] = lo;
            } else {
                const int r = idx - H2 * H1;
                const int n = r & 255, k = r >> 8;
                __nv_bfloat16 hi, lo;
                split_bf16(__ldg(&W3[k * H3 + n]), hi, lo);
                g_w3t_hi[n * LDA + k] = hi;
                g_w3t_lo[n * LDA + k] = lo;
            }
        }
    }
}

// ================= 2) Radius search (first K in index order) =================
__global__ __launch_bounds__(256)
void radius_kernel(const float* __restrict__ pos, float* __restrict__ out, long long out_size) {
    const int warp = (blockIdx.x * blockDim.x + threadIdx.x) >> 5;
    const int lane = threadIdx.x & 31;
    if (warp >= MTOT) return;
    const int b  = warp >> 10;
    const float* p = pos + (size_t)b * NB * 3;

    const int selIdx = g_sel[warp];
    const float qx = p[selIdx * 3 + 0];
    const float qy = p[selIdx * 3 + 1];
    const float qz = p[selIdx * 3 + 2];

    if (lane == 0) {
        g_qpos[warp * 3 + 0] = qx;
        g_qpos[warp * 3 + 1] = qy;
        g_qpos[warp * 3 + 2] = qz;
        if (out_size >= (long long)(POS_OFF + POS_ELEMS)) {
            out[POS_OFF + (size_t)warp * 3 + 0] = qx;
            out[POS_OFF + (size_t)warp * 3 + 1] = qy;
            out[POS_OFF + (size_t)warp * 3 + 2] = qz;
        }
        if (out_size >= (long long)(BATCH_OFF + BATCH_ELEMS)) {
            out[BATCH_OFF + warp] = (float)b;
        }
    }

    const float R2 = 0.04f;
    int cnt = 0;
    for (int base = 0; base < NB; base += 32) {
        const int j = base + lane;
        float d2 = d2_exact(p[j * 3 + 0] - qx, p[j * 3 + 1] - qy, p[j * 3 + 2] - qz);
        const bool in = (d2 <= R2);
        const unsigned msk = __ballot_sync(0xffffffffu, in);
        if (in) {
            int r = cnt + __popc(msk & ((1u << lane) - 1u));
            if (r < KNB) g_nbr[warp * KNB + r] = j;
        }
        cnt += __popc(msk);
        if (cnt >= KNB) break;
    }
    if (lane == 0) g_cnt[warp] = cnt < KNB ? cnt : KNB;
}

// ================= 3) Conv via warp MMA (bf16x3) =================
// Block = 2 centroids (M = 128 neighbor rows). 256 threads = 8 warps.
// smem: A_hi/A_lo [128][LDA] bf16, B_hi/B_lo [256][LDA] bf16, omax[512] int, w1r[384] f32
#define OFF_A_HI   0
#define OFF_A_LO   34816
#define OFF_B_HI   69632
#define OFF_B_LO   139264
#define OFF_OMAX   208896
#define OFF_W1R    210944
#define CONV_SMEM  212480

__global__ __launch_bounds__(256, 1)
void conv_kernel(const float* __restrict__ pos, const float* __restrict__ W1,
                 const float* __restrict__ b2, const float* __restrict__ b3,
                 float* __restrict__ out) {
    extern __shared__ char sm[];
    const uint32_t sb = smem_u32(sm);
    __nv_bfloat16* Ahi = (__nv_bfloat16*)(sm + OFF_A_HI);
    __nv_bfloat16* Alo = (__nv_bfloat16*)(sm + OFF_A_LO);
    int*   omax = (int*)(sm + OFF_OMAX);
    float* w1r  = (float*)(sm + OFF_W1R);

    const int tid  = threadIdx.x;
    const int warp = tid >> 5;
    const int lane = tid & 31;
    const int g    = lane >> 2;
    const int tig  = lane & 3;
    const int c0   = blockIdx.x * 2;
    const int gp   = (c0 >> 10) * NB;

    for (int i = tid; i < 512; i += 256) omax[i] = 0;
    if (tid < 128) {
        w1r[tid]       = __ldg(&W1[64 * H1 + tid]);
        w1r[128 + tid] = __ldg(&W1[65 * H1 + tid]);
        w1r[256 + tid] = __ldg(&W1[66 * H1 + tid]);
    }
    __syncthreads();

    // ---- phase 1: build A = h1 split (hi/lo bf16); copy W2T into B ----
    {
        const int m    = tid >> 1;
        const int hf   = tid & 1;
        const int ci   = c0 + (m >> 6);
        const int slot = m & 63;
        const int cnt  = g_cnt[ci];
        const bool valid = slot < cnt;
        const int j = valid ? (g_nbr[ci * KNB + slot] + gp) : gp;
        const float rx = __ldg(&pos[j * 3 + 0]) - g_qpos[ci * 3 + 0];
        const float ry = __ldg(&pos[j * 3 + 1]) - g_qpos[ci * 3 + 1];
        const float rz = __ldg(&pos[j * 3 + 2]) - g_qpos[ci * 3 + 2];
        const float* xrow = g_xw1 + (size_t)j * H1;
#pragma unroll 4
        for (int c4 = hf * 64; c4 < hf * 64 + 64; c4 += 4) {
            const float4 xv = __ldg((const float4*)(xrow + c4));
            const float xe[4] = {xv.x, xv.y, xv.z, xv.w};
            __nv_bfloat16 hi[4], lo[4];
#pragma unroll
            for (int e = 0; e < 4; e++) {
                const int t = c4 + e;
                float v = xe[e];
                v = fmaf(rx, w1r[t], v);
                v = fmaf(ry, w1r[128 + t], v);
                v = fmaf(rz, w1r[256 + t], v);
                v = fmaxf(v, 0.0f);
                if (!valid) v = 0.0f;
                split_bf16(v, hi[e], lo[e]);
            }
            *(uint32_t*)(Ahi + m * LDA + c4)     = packbf(hi[0], hi[1]);
            *(uint32_t*)(Ahi + m * LDA + c4 + 2) = packbf(hi[2], hi[3]);
            *(uint32_t*)(Alo + m * LDA + c4)     = packbf(lo[0], lo[1]);
            *(uint32_t*)(Alo + m * LDA + c4 + 2) = packbf(lo[2], lo[3]);
        }
    }
    {
        const float4* s0 = (const float4*)g_w2t_hi;
        const float4* s1 = (const float4*)g_w2t_lo;
        float4* d0 = (float4*)(sm + OFF_B_HI);
        float4* d1 = (float4*)(sm + OFF_B_LO);
        for (int i = tid; i < (H2 * LDA * 2) / 16; i += 256) { d0[i] = s0[i]; d1[i] = s1[i]; }
    }
    __syncthreads();

    const uint32_t aAhi = sb + OFF_A_HI, aAlo = sb + OFF_A_LO;
    const uint32_t aBhi = sb + OFF_B_HI, aBlo = sb + OFF_B_LO;

    // ---- GEMM1: h2_pre[128x128] = A[128x128] @ W2 (bf16x3) ----
    float d1r[2][8][4] = {};
    {
        const int mw = (warp & 3) * 32;
        const int nw = (warp >> 2) * 64;
        for (int ks = 0; ks < 8; ks++) {
            const uint32_t colo = (uint32_t)(ks * 16 + (lane >> 4) * 8) * 2;
            uint32_t ah[2][4], al[2][4];
#pragma unroll
            for (int mf = 0; mf < 2; mf++) {
                const uint32_t ro = (uint32_t)(mw + mf * 16 + (lane & 15)) * (LDA * 2);
                ldmat4(ah[mf], aAhi + ro + colo);
                ldmat4(al[mf], aAlo + ro + colo);
            }
            uint32_t bh[8][2], bl[8][2];
#pragma unroll
            for (int np = 0; np < 4; np++) {
                const uint32_t ro = (uint32_t)(nw + np * 16 + (lane & 15)) * (LDA * 2);
                uint32_t r[4];
                ldmat4(r, aBhi + ro + colo);
                bh[2 * np][0] = r[0]; bh[2 * np][1] = r[2];
                bh[2 * np + 1][0] = r[1]; bh[2 * np + 1][1] = r[3];
                ldmat4(r, aBlo + ro + colo);
                bl[2 * np][0] = r[0]; bl[2 * np][1] = r[2];
                bl[2 * np + 1][0] = r[1]; bl[2 * np + 1][1] = r[3];
            }
#pragma unroll
            for (int mf = 0; mf < 2; mf++)
#pragma unroll
                for (int nf = 0; nf < 8; nf++) {
                    mma16816(d1r[mf][nf], ah[mf], bh[nf]);
                    mma16816(d1r[mf][nf], ah[mf], bl[nf]);
                    mma16816(d1r[mf][nf], al[mf], bh[nf]);
                }
        }
    }
    __syncthreads();   // all reads of h1 (A) and W2T (B) complete

    // ---- epilogue 1: h2 = relu(D1 + b2) -> split back into A; copy W3T ----
    {
        const int mw = (warp & 3) * 32;
        const int nw = (warp >> 2) * 64;
#pragma unroll
        for (int mf = 0; mf < 2; mf++) {
            const int row0 = mw + mf * 16 + g;
#pragma unroll
            for (int nf = 0; nf < 8; nf++) {
                const int col = nw + nf * 8 + tig * 2;
                const float bb0 = __ldg(&b2[col]);
                const float bb1 = __ldg(&b2[col + 1]);
                const float v00 = fmaxf(d1r[mf][nf][0] + bb0, 0.0f);
                const float v01 = fmaxf(d1r[mf][nf][1] + bb1, 0.0f);
                const float v10 = fmaxf(d1r[mf][nf][2] + bb0, 0.0f);
                const float v11 = fmaxf(d1r[mf][nf][3] + bb1, 0.0f);
                __nv_bfloat16 h0, l0, h1b, l1b, h2b, l2b, h3b, l3b;
                split_bf16(v00, h0, l0);
                split_bf16(v01, h1b, l1b);
                split_bf16(v10, h2b, l2b);
                split_bf16(v11, h3b, l3b);
                *(uint32_t*)(Ahi + row0 * LDA + col)       = packbf(h0, h1b);
                *(uint32_t*)(Alo + row0 * LDA + col)       = packbf(l0, l1b);
                *(uint32_t*)(Ahi + (row0 + 8) * LDA + col) = packbf(h2b, h3b);
                *(uint32_t*)(Alo + (row0 + 8) * LDA + col) = packbf(l2b, l3b);
            }
        }
    }
    {
        const float4* s0 = (const float4*)g_w3t_hi;
        const float4* s1 = (const float4*)g_w3t_lo;
        float4* d0 = (float4*)(sm + OFF_B_HI);
        float4* d1 = (float4*)(sm + OFF_B_LO);
        for (int i = tid; i < (H3 * LDA * 2) / 16; i += 256) { d0[i] = s0[i]; d1[i] = s1[i]; }
    }
    __syncthreads();

    // ---- GEMM2 + fused masked max epilogue ----
    const int cnt0 = g_cnt[c0];
    const int cnt1 = g_cnt[c0 + 1];
#pragma unroll
    for (int rep = 0; rep < 2; rep++) {
        const int T  = warp + 8 * rep;
        const int m0 = (T & 3) * 32;
        const int n0 = (T >> 2) * 64;
        float d2r[2][8][4] = {};
        for (int ks = 0; ks < 8; ks++) {
            const uint32_t colo = (uint32_t)(ks * 16 + (lane >> 4) * 8) * 2;
            uint32_t ah[2][4], al[2][4];
#pragma unroll
            for (int mf = 0; mf < 2; mf++) {
                const uint32_t ro = (uint32_t)(m0 + mf * 16 + (lane & 15)) * (LDA * 2);
                ldmat4(ah[mf], aAhi + ro + colo);
                ldmat4(al[mf], aAlo + ro + colo);
            }
            uint32_t bh[8][2], bl[8][2];
#pragma unroll
            for (int np = 0; np < 4; np++) {
                const uint32_t ro = (uint32_t)(n0 + np * 16 + (lane & 15)) * (LDA * 2);
                uint32_t r[4];
                ldmat4(r, aBhi + ro + colo);
                bh[2 * np][0] = r[0]; bh[2 * np][1] = r[2];
                bh[2 * np + 1][0] = r[1]; bh[2 * np + 1][1] = r[3];
                ldmat4(r, aBlo + ro + colo);
                bl[2 * np][0] = r[0]; bl[2 * np][1] = r[2];
                bl[2 * np + 1][0] = r[1]; bl[2 * np + 1][1] = r[3];
            }
#pragma unroll
            for (int mf = 0; mf < 2; mf++)
#pragma unroll
                for (int nf = 0; nf < 8; nf++) {
                    mma16816(d2r[mf][nf], ah[mf], bh[nf]);
                    mma16816(d2r[mf][nf], ah[mf], bl[nf]);
                    mma16816(d2r[mf][nf], al[mf], bh[nf]);
                }
        }
        // masked max over the 32 rows this warp owns
        const int count = (m0 >= 64) ? cnt1 : cnt0;
        const int cbase = (m0 >= 64) ? 256 : 0;
        const int rr = (m0 & 32) + g;               // slot of mf0/row0
        const bool v0 = rr < count;
        const bool v1 = rr + 8 < count;
        const bool v2 = rr + 16 < count;
        const bool v3 = rr + 24 < count;
#pragma unroll
        for (int nf = 0; nf < 8; nf++) {
            const int col = n0 + nf * 8 + tig * 2;
            const float bb0 = __ldg(&b3[col]);
            const float bb1 = __ldg(&b3[col + 1]);
            float mx0 = 0.0f, mx1 = 0.0f;
            if (v0) { mx0 = fmaxf(mx0, d2r[0][nf][0] + bb0); mx1 = fmaxf(mx1, d2r[0][nf][1] + bb1); }
            if (v1) { mx0 = fmaxf(mx0, d2r[0][nf][2] + bb0); mx1 = fmaxf(mx1, d2r[0][nf][3] + bb1); }
            if (v2) { mx0 = fmaxf(mx0, d2r[1][nf][0] + bb0); mx1 = fmaxf(mx1, d2r[1][nf][1] + bb1); }
            if (v3) { mx0 = fmaxf(mx0, d2r[1][nf][2] + bb0); mx1 = fmaxf(mx1, d2r[1][nf][3] + bb1); }
            // (values clamped at 0 == relu, since mx starts at 0 and final max >= 0)
#pragma unroll
            for (int off = 4; off <= 16; off <<= 1) {
                mx0 = fmaxf(mx0, __shfl_xor_sync(0xffffffffu, mx0, off));
                mx1 = fmaxf(mx1, __shfl_xor_sync(0xffffffffu, mx1, off));
            }
            if (lane < 4) {
                atomicMax(&omax[cbase + col],     __float_as_int(mx0));
                atomicMax(&omax[cbase + col + 1], __float_as_int(mx1));
            }
        }
    }
    __syncthreads();

    for (int i = tid; i < 512; i += 256)
        out[(size_t)(c0 + (i >> 8)) * H3 + (i & 255)] = __int_as_float(omax[i]);
}

// ================= launch =================
extern "C" void kernel_launch(void* const* d_in, const int* in_sizes, int n_in,
                              void* d_out, int out_size) {
    const float* x   = (const float*)d_in[0];
    const float* pos = (const float*)d_in[1];
    // d_in[2] = batch (int32), unused: clouds contiguous & equal-sized
    const float* W1  = (const float*)d_in[3];
    const float* b1  = (const float*)d_in[4];
    const float* W2  = (const float*)d_in[5];
    const float* b2  = (const float*)d_in[6];
    const float* W3  = (const float*)d_in[7];
    const float* b3  = (const float*)d_in[8];
    float* out = (float*)d_out;

    cudaFuncSetAttribute(conv_kernel, cudaFuncAttributeMaxDynamicSharedMemorySize, CONV_SMEM);

    fused_fps_prep<<<4 + NPREP, 256>>>(pos, x, W1, b1, W2, W3);
    radius_kernel<<<MTOT / 8, 256>>>(pos, out, (long long)out_size);
    conv_kernel<<<MTOT / 2, 256, CONV_SMEM>>>(pos, W1, b2, b3, out);
}